// round 2
// baseline (speedup 1.0000x reference)
#include <cuda_runtime.h>
#include <cmath>

// ---------------- problem constants ----------------
#define HID   2048
#define SEQL  1024
#define NBAT  4
#define NHEAD 16
#define DHEAD 128
#define MTOK  4096          // NBAT*SEQL
#define BHTOT 64            // NBAT*NHEAD

// ---------------- scratch (device globals; no allocations allowed) ----------
__device__ float g_y   [(size_t)MTOK * HID];          // LN output       32MB
__device__ float g_qkv [(size_t)MTOK * 3 * HID];      // QKV             96MB
__device__ float g_Q   [(size_t)BHTOT * SEQL * DHEAD];// packed Q        32MB
__device__ float g_K   [(size_t)BHTOT * SEQL * DHEAD];// packed K        32MB
__device__ float g_Vt  [(size_t)BHTOT * DHEAD * SEQL];// packed V^T      32MB
__device__ float g_S   [(size_t)BHTOT * SEQL * SEQL]; // scores         256MB
__device__ float g_ctx [(size_t)BHTOT * SEQL * DHEAD];// attn output     32MB
__device__ float g_ctxr[(size_t)MTOK * HID];          // ctx re-packed   32MB
__device__ float g_x2  [(size_t)MTOK * HID];          // post-MHSA resid 32MB
__device__ float g_mlp [(size_t)MTOK * 4 * HID];      // gelu output    128MB

// ---------------- GEMM: C[m,n] = epilogue( alpha * sum_k A[m,k]*B[n,k] ) ----
// TN form: A is MxK row-major, B is NxK row-major. TF32 tensor cores.
#define BM 128
#define BN 128
#define BK 32
#define BKP 36                 // padded K stride (bank-conflict free, 16B aligned)
#define STAGE_F (BM * BKP)     // floats per stage per operand
#define GEMM_SMEM_BYTES (4 * STAGE_F * 4)  // 2 stages * (A+B) = 73728 B

__device__ __forceinline__ unsigned f2tf32(float f) {
    unsigned u;
    asm("cvt.rna.tf32.f32 %0, %1;" : "=r"(u) : "f"(f));
    return u;
}

// MODE 0: C = alpha*acc
// MODE 1: C = alpha*acc + rscale*resid
// MODE 2: C = gelu_us(alpha*acc + bscale*bias[n])       (gelu_us = v*Phi(v)*inv_rms)
// MODE 3: C = alpha*acc + bscale*bias[n] + rscale*resid
template <int MODE>
__global__ void __launch_bounds__(256, 2)
gemm_tn(const float* __restrict__ A, const float* __restrict__ B,
        float* __restrict__ C,
        int M, int N, int K,
        long sA, long sB, long sC,
        float alpha,
        const float* __restrict__ bias, float bscale,
        const float* __restrict__ resid, float rscale,
        float inv_rms)
{
    extern __shared__ float smem[];
    float* As = smem;                   // [2][BM][BKP]
    float* Bs = smem + 2 * STAGE_F;     // [2][BN][BKP]

    const int m0 = blockIdx.y * BM;
    const int n0 = blockIdx.x * BN;
    A += blockIdx.z * sA + (long)m0 * K;
    B += blockIdx.z * sB + (long)n0 * K;
    C += blockIdx.z * sC;
    const float* Rz = (MODE == 1 || MODE == 3) ? resid + blockIdx.z * sC : nullptr;

    const int tid  = threadIdx.x;
    const int lane = tid & 31;
    const int warp = tid >> 5;
    const int wm = warp >> 2;          // 0..1  (64 rows each)
    const int wn = warp & 3;           // 0..3  (32 cols each)
    const int g  = lane >> 2;          // 0..7
    const int t4 = lane & 3;           // 0..3

    const int lrow = tid >> 3;         // 0..31
    const int lcol = (tid & 7) * 4;    // 0..28

    float acc[4][4][4];
#pragma unroll
    for (int i = 0; i < 4; i++)
#pragma unroll
        for (int j = 0; j < 4; j++)
#pragma unroll
            for (int c = 0; c < 4; c++) acc[i][j][c] = 0.f;

    const int KT = K / BK;

    auto issue = [&](int kt, int buf) {
        const float* Ag = A + kt * BK;
        const float* Bg = B + kt * BK;
        float* Asb = As + buf * STAGE_F;
        float* Bsb = Bs + buf * STAGE_F;
#pragma unroll
        for (int i = 0; i < 4; i++) {
            int r = lrow + i * 32;
            unsigned da = (unsigned)__cvta_generic_to_shared(&Asb[r * BKP + lcol]);
            asm volatile("cp.async.cg.shared.global [%0], [%1], 16;\n"
                         :: "r"(da), "l"(Ag + (long)r * K + lcol) : "memory");
            unsigned db = (unsigned)__cvta_generic_to_shared(&Bsb[r * BKP + lcol]);
            asm volatile("cp.async.cg.shared.global [%0], [%1], 16;\n"
                         :: "r"(db), "l"(Bg + (long)r * K + lcol) : "memory");
        }
        asm volatile("cp.async.commit_group;\n" ::: "memory");
    };

    issue(0, 0);

    for (int kt = 0; kt < KT; kt++) {
        int buf = kt & 1;
        asm volatile("cp.async.wait_group 0;\n" ::: "memory");
        __syncthreads();
        if (kt + 1 < KT) issue(kt + 1, buf ^ 1);

        const float* Asb = As + buf * STAGE_F;
        const float* Bsb = Bs + buf * STAGE_F;

#pragma unroll
        for (int ks = 0; ks < 4; ks++) {
            const int kb = ks * 8;
            unsigned af[4][4], bf[4][2];
#pragma unroll
            for (int mt = 0; mt < 4; mt++) {
                int r = wm * 64 + mt * 16;
                af[mt][0] = f2tf32(Asb[(r + g    ) * BKP + kb + t4]);
                af[mt][1] = f2tf32(Asb[(r + g + 8) * BKP + kb + t4]);
                af[mt][2] = f2tf32(Asb[(r + g    ) * BKP + kb + t4 + 4]);
                af[mt][3] = f2tf32(Asb[(r + g + 8) * BKP + kb + t4 + 4]);
            }
#pragma unroll
            for (int nt = 0; nt < 4; nt++) {
                int c = wn * 32 + nt * 8;
                bf[nt][0] = f2tf32(Bsb[(c + g) * BKP + kb + t4]);
                bf[nt][1] = f2tf32(Bsb[(c + g) * BKP + kb + t4 + 4]);
            }
#pragma unroll
            for (int mt = 0; mt < 4; mt++)
#pragma unroll
                for (int nt = 0; nt < 4; nt++) {
                    asm volatile(
                        "mma.sync.aligned.m16n8k8.row.col.f32.tf32.tf32.f32 "
                        "{%0,%1,%2,%3}, {%4,%5,%6,%7}, {%8,%9}, {%0,%1,%2,%3};\n"
                        : "+f"(acc[mt][nt][0]), "+f"(acc[mt][nt][1]),
                          "+f"(acc[mt][nt][2]), "+f"(acc[mt][nt][3])
                        : "r"(af[mt][0]), "r"(af[mt][1]), "r"(af[mt][2]), "r"(af[mt][3]),
                          "r"(bf[nt][0]), "r"(bf[nt][1]));
                }
        }
        __syncthreads();
    }

    // ---------------- epilogue ----------------
#pragma unroll
    for (int mt = 0; mt < 4; mt++) {
        int rbase = m0 + wm * 64 + mt * 16;
#pragma unroll
        for (int nt = 0; nt < 4; nt++) {
            int c0 = n0 + wn * 32 + nt * 8 + 2 * t4;
#pragma unroll
            for (int half = 0; half < 2; half++) {
                int r = rbase + g + half * 8;
                float v0 = acc[mt][nt][half * 2 + 0] * alpha;
                float v1 = acc[mt][nt][half * 2 + 1] * alpha;
                if (MODE == 2 || MODE == 3) {
                    v0 += bias[c0] * bscale;
                    v1 += bias[c0 + 1] * bscale;
                }
                if (MODE == 2) {
                    v0 = v0 * normcdff(v0) * inv_rms;
                    v1 = v1 * normcdff(v1) * inv_rms;
                }
                long idx = (long)r * N + c0;
                if (MODE == 1 || MODE == 3) {
                    v0 += Rz[idx] * rscale;
                    v1 += Rz[idx + 1] * rscale;
                }
                C[idx]     = v0;
                C[idx + 1] = v1;
            }
        }
    }
}

// ---------------- LayerNorm: one block per row (H=2048) --------------------
__global__ void ln_kernel(const float* __restrict__ xin,
                          const float* __restrict__ w,
                          const float* __restrict__ b,
                          float* __restrict__ y)
{
    __shared__ float red[16];
    const long row = blockIdx.x;
    const float4* xr = (const float4*)(xin + row * HID);
    const int t = threadIdx.x;  // 256 threads, 8 floats each

    float4 v0 = xr[t];
    float4 v1 = xr[t + 256];
    float s  = v0.x + v0.y + v0.z + v0.w + v1.x + v1.y + v1.z + v1.w;
    float sq = v0.x*v0.x + v0.y*v0.y + v0.z*v0.z + v0.w*v0.w
             + v1.x*v1.x + v1.y*v1.y + v1.z*v1.z + v1.w*v1.w;

#pragma unroll
    for (int o = 16; o; o >>= 1) {
        s  += __shfl_xor_sync(0xffffffffu, s,  o);
        sq += __shfl_xor_sync(0xffffffffu, sq, o);
    }
    if ((t & 31) == 0) { red[t >> 5] = s; red[8 + (t >> 5)] = sq; }
    __syncthreads();
    if (t == 0) {
        float S = 0.f, Q = 0.f;
        for (int i = 0; i < 8; i++) { S += red[i]; Q += red[8 + i]; }
        red[0] = S; red[8] = Q;
    }
    __syncthreads();
    const float mean = red[0] * (1.0f / HID);
    float var = red[8] * (1.0f / HID) - mean * mean;
    var = fmaxf(var, 0.0f);
    const float rstd = rsqrtf(var + 1e-5f);

    float4* yr = (float4*)(y + row * HID);
    const float4 w0 = ((const float4*)w)[t];
    const float4 w1 = ((const float4*)w)[t + 256];
    const float4 b0 = ((const float4*)b)[t];
    const float4 b1 = ((const float4*)b)[t + 256];
    float4 o0, o1;
    o0.x = (v0.x - mean) * rstd * w0.x + b0.x;
    o0.y = (v0.y - mean) * rstd * w0.y + b0.y;
    o0.z = (v0.z - mean) * rstd * w0.z + b0.z;
    o0.w = (v0.w - mean) * rstd * w0.w + b0.w;
    o1.x = (v1.x - mean) * rstd * w1.x + b1.x;
    o1.y = (v1.y - mean) * rstd * w1.y + b1.y;
    o1.z = (v1.z - mean) * rstd * w1.z + b1.z;
    o1.w = (v1.w - mean) * rstd * w1.w + b1.w;
    yr[t]       = o0;
    yr[t + 256] = o1;
}

// ---------------- softmax over rows of 1024 (normalized; S/sqrt(e) folded
// into the attn@V GEMM alpha) ------------------------------------------------
__global__ void softmax_kernel(float* __restrict__ sc)
{
    __shared__ float red[16];
    const size_t row = blockIdx.x;
    float4* p = (float4*)(sc + row * (size_t)SEQL);
    const int t = threadIdx.x;   // 256 threads, 4 floats each

    float4 v = p[t];
    float mx = fmaxf(fmaxf(v.x, v.y), fmaxf(v.z, v.w));
#pragma unroll
    for (int o = 16; o; o >>= 1) mx = fmaxf(mx, __shfl_xor_sync(0xffffffffu, mx, o));
    if ((t & 31) == 0) red[t >> 5] = mx;
    __syncthreads();
    if (t == 0) {
        float m = red[0];
        for (int i = 1; i < 8; i++) m = fmaxf(m, red[i]);
        red[0] = m;
    }
    __syncthreads();
    mx = red[0];

    float e0 = expf(v.x - mx), e1 = expf(v.y - mx);
    float e2 = expf(v.z - mx), e3 = expf(v.w - mx);
    float s = e0 + e1 + e2 + e3;
#pragma unroll
    for (int o = 16; o; o >>= 1) s += __shfl_xor_sync(0xffffffffu, s, o);
    if ((t & 31) == 0) red[8 + (t >> 5)] = s;
    __syncthreads();
    if (t == 0) {
        float S = 0.f;
        for (int i = 0; i < 8; i++) S += red[8 + i];
        red[8] = S;
    }
    __syncthreads();
    const float inv = 1.0f / red[8];

    float4 o;
    o.x = e0 * inv; o.y = e1 * inv; o.z = e2 * inv; o.w = e3 * inv;
    p[t] = o;
}

// ---------------- pack qkv -> Q[bh,s,d], K[bh,s,d], Vt[bh,d,s] --------------
__global__ void pack_qkv(const float* __restrict__ qkv)
{
    const int t = blockIdx.x * 256 + threadIdx.x;  // BHTOT*SEQL*DHEAD = 8388608
    const int d  = t & 127;
    const int s  = (t >> 7) & 1023;
    const int bh = t >> 17;
    const int b  = bh >> 4, h = bh & 15;
    const long m = (long)b * SEQL + s;
    const long base = m * (3 * HID) + (long)h * DHEAD + d;
    const long o = (long)bh * (SEQL * DHEAD) + (long)s * DHEAD + d;
    g_Q[o] = qkv[base];
    g_K[o] = qkv[base + HID];
    g_Vt[(long)bh * (SEQL * DHEAD) + (long)d * SEQL + s] = qkv[base + 2 * HID];
}

// ---------------- repack ctx[bh,s,d] -> ctxr[b*s, h*d] ----------------------
__global__ void repack_ctx()
{
    const int t = blockIdx.x * 256 + threadIdx.x;  // MTOK*HID = 8388608
    const int hc = t & 2047;
    const int m  = t >> 11;
    const int d = hc & 127, h = hc >> 7;
    const int b = m >> 10, s = m & 1023;
    g_ctxr[t] = g_ctx[((long)(b * NHEAD + h)) * (SEQL * DHEAD) + (long)s * DHEAD + d];
}

// ---------------- launch ----------------------------------------------------
extern "C" void kernel_launch(void* const* d_in, const int* in_sizes, int n_in,
                              void* d_out, int out_size)
{
    const float* x     = (const float*)d_in[0];
    const float* ln1w  = (const float*)d_in[1];
    const float* ln1b  = (const float*)d_in[2];
    const float* wqkv  = (const float*)d_in[3];
    const float* wo    = (const float*)d_in[4];
    const float* ln2w  = (const float*)d_in[5];
    const float* ln2b  = (const float*)d_in[6];
    const float* w1    = (const float*)d_in[7];
    const float* b1    = (const float*)d_in[8];
    const float* w2    = (const float*)d_in[9];
    const float* b2    = (const float*)d_in[10];
    float* out = (float*)d_out;

    // GELU_RMS via the exact same quadrature as the reference
    double ssum = 0.0;
    const double dx = 24.0 / 48000.0;
    for (int i = 0; i <= 48000; i++) {
        double xx  = -12.0 + dx * i;
        double pdf = exp(-0.5 * xx * xx) / sqrt(2.0 * M_PI);
        double cdf = 0.5 * (1.0 + erf(xx / sqrt(2.0)));
        double gg  = xx * cdf;
        ssum += gg * gg * pdf;
    }
    const float inv_rms = (float)(1.0 / sqrt(ssum * dx));

    float *py, *pqkv, *pQ, *pK, *pVt, *pS, *pctx, *pctxr, *px2, *pmlp;
    cudaGetSymbolAddress((void**)&py,    g_y);
    cudaGetSymbolAddress((void**)&pqkv,  g_qkv);
    cudaGetSymbolAddress((void**)&pQ,    g_Q);
    cudaGetSymbolAddress((void**)&pK,    g_K);
    cudaGetSymbolAddress((void**)&pVt,   g_Vt);
    cudaGetSymbolAddress((void**)&pS,    g_S);
    cudaGetSymbolAddress((void**)&pctx,  g_ctx);
    cudaGetSymbolAddress((void**)&pctxr, g_ctxr);
    cudaGetSymbolAddress((void**)&px2,   g_x2);
    cudaGetSymbolAddress((void**)&pmlp,  g_mlp);

    cudaFuncSetAttribute(gemm_tn<0>, cudaFuncAttributeMaxDynamicSharedMemorySize, GEMM_SMEM_BYTES);
    cudaFuncSetAttribute(gemm_tn<1>, cudaFuncAttributeMaxDynamicSharedMemorySize, GEMM_SMEM_BYTES);
    cudaFuncSetAttribute(gemm_tn<2>, cudaFuncAttributeMaxDynamicSharedMemorySize, GEMM_SMEM_BYTES);
    cudaFuncSetAttribute(gemm_tn<3>, cudaFuncAttributeMaxDynamicSharedMemorySize, GEMM_SMEM_BYTES);

    const float rs_h   = (float)(1.0 / sqrt((double)HID));        // h^-0.5
    const float rs_d   = (float)(1.0 / sqrt((double)DHEAD));      // d^-0.5
    const float a_ctx  = (float)(32.0 / exp(0.5));                // sqrt(S)/sqrt(e)
    const float a_o    = (float)(sqrt(0.01) / sqrt((double)HID)); // h^-0.5 * sqrt(tau1)
    const float r_o    = (float)sqrt(0.99);                       // sqrt(1-tau1)
    const float a_w2   = (float)(sqrt(0.5) / sqrt((double)(4 * HID)));
    const float b_w2   = (float)sqrt(0.5);
    const float r_w2   = (float)sqrt(0.5);

    // 1. LN1
    ln_kernel<<<MTOK, 256>>>(x, ln1w, ln1b, py);
    // 2. QKV = LN1(x) @ Wqkv^T * h^-0.5           [4096 x 6144]
    gemm_tn<0><<<dim3(48, 32, 1), 256, GEMM_SMEM_BYTES>>>(
        py, wqkv, pqkv, MTOK, 3 * HID, HID, 0, 0, 0,
        rs_h, nullptr, 0.f, nullptr, 0.f, 0.f);
    // 3. pack q/k/v per (batch, head); V transposed
    pack_qkv<<<32768, 256>>>(pqkv);
    // 4. scores = Q K^T * d^-0.5                  [64 x 1024 x 1024]
    gemm_tn<0><<<dim3(8, 8, BHTOT), 256, GEMM_SMEM_BYTES>>>(
        pQ, pK, pS, SEQL, SEQL, DHEAD,
        (long)SEQL * DHEAD, (long)SEQL * DHEAD, (long)SEQL * SEQL,
        rs_d, nullptr, 0.f, nullptr, 0.f, 0.f);
    // 5. row softmax (normalized probs)
    softmax_kernel<<<BHTOT * SEQL, 256>>>(pS);
    // 6. ctx = softmax @ V * sqrt(S)/sqrt(e)      [64 x 1024 x 128]
    gemm_tn<0><<<dim3(1, 8, BHTOT), 256, GEMM_SMEM_BYTES>>>(
        pS, pVt, pctx, SEQL, DHEAD, SEQL,
        (long)SEQL * SEQL, (long)SEQL * DHEAD, (long)SEQL * DHEAD,
        a_ctx, nullptr, 0.f, nullptr, 0.f, 0.f);
    // 7. repack ctx to [token, hidden]
    repack_ctx<<<32768, 256>>>();
    // 8. x2 = (ctx @ Wo^T) * h^-0.5*sqrt(tau) + x*sqrt(1-tau)
    gemm_tn<1><<<dim3(16, 32, 1), 256, GEMM_SMEM_BYTES>>>(
        pctxr, wo, px2, MTOK, HID, HID, 0, 0, 0,
        a_o, nullptr, 0.f, x, r_o, 0.f);
    // 9. LN2
    ln_kernel<<<MTOK, 256>>>(px2, ln2w, ln2b, py);
    // 10. mlp = gelu_us( LN2 @ W1^T * h^-0.5 + b1 )   [4096 x 8192]
    gemm_tn<2><<<dim3(64, 32, 1), 256, GEMM_SMEM_BYTES>>>(
        py, w1, pmlp, MTOK, 4 * HID, HID, 0, 0, 0,
        rs_h, b1, 1.0f, nullptr, 0.f, inv_rms);
    // 11. out = (mlp @ W2^T * (4h)^-0.5 + b2)*sqrt(.5) + x2*sqrt(.5)
    gemm_tn<3><<<dim3(16, 32, 1), 256, GEMM_SMEM_BYTES>>>(
        pmlp, w2, out, MTOK, HID, 4 * HID, 0, 0, 0,
        a_w2, b2, b_w2, px2, r_w2, 0.f);
}

// round 6
// speedup vs baseline: 1.1520x; 1.1520x over previous
#include <cuda_runtime.h>
#include <cmath>
#include <cstdint>

// ---------------- problem constants ----------------
#define HID   2048
#define SEQL  1024
#define NBAT  4
#define NHEAD 16
#define DHEAD 128
#define MTOK  4096          // NBAT*SEQL
#define BHTOT 64            // NBAT*NHEAD

#define MF ((size_t)1048576)

// ---------------- single flat scratch: 176M floats = 704MB ------------------
// Layout (float offsets):
//   y     [0,        8M )   LN output (tf32-rounded)
//   qkv   [8M,      32M )   QKV output
//   Q     [32M,     40M )   packed Q (rounded)
//   K     [40M,     48M )   packed K (rounded)
//   Vt    [48M,     56M )   packed V^T (rounded)
//   S     [56M,    120M )   scores/probs (steps 4-6); then w1_r at 56M (16M),
//                           w2_r at 72M (16M) rounded AFTER step 6
//   ctx   [120M,   128M )   attn output
//   ctxr  [128M,   136M )   ctx re-packed (rounded)
//   x2    [136M,   144M )   post-MHSA residual
//   mlp   [144M,   176M )   gelu output (step 10+); also hosts wqkv_r at 144M
//                           (12M) and wo_r at 156M (4M) during steps 0-8
__device__ __align__(16) float g_scratch[176 * MF];

#define OFF_Y     (0 * MF)
#define OFF_QKV   (8 * MF)
#define OFF_Q     (32 * MF)
#define OFF_K     (40 * MF)
#define OFF_VT    (48 * MF)
#define OFF_S     (56 * MF)
#define OFF_W1R   (56 * MF)     // aliases S (rounded after S's last read)
#define OFF_W2R   (72 * MF)     // aliases S
#define OFF_CTX   (120 * MF)
#define OFF_CTXR  (128 * MF)
#define OFF_X2    (136 * MF)
#define OFF_MLP   (144 * MF)
#define OFF_WQKVR (144 * MF)    // aliases mlp (mlp written at step 10)
#define OFF_WOR   (156 * MF)    // aliases mlp

__device__ __forceinline__ float f2tf32f(float f) {
    unsigned u;
    asm("cvt.rna.tf32.f32 %0, %1;" : "=r"(u) : "f"(f));
    return __uint_as_float(u);
}

// ---------------- GEMM: C[m,n] = epilogue( alpha * sum_k A[m,k]*B[n,k] ) ----
// TN form: A is MxK row-major, B is NxK row-major, both PRE-ROUNDED to tf32.
#define BM 128
#define BN 128
#define BK 32
#define BKP 36                 // padded K stride (bank-conflict free, 16B aligned)
#define STAGE_F (BM * BKP)     // floats per stage per operand
#define GEMM_SMEM_BYTES (4 * STAGE_F * 4)  // 2 stages * (A+B) = 73728 B

// MODE 0: C = alpha*acc
// MODE 1: C = alpha*acc + rscale*resid
// MODE 2: C = round_tf32( gelu_us(alpha*acc + bscale*bias[n]) )
// MODE 3: C = alpha*acc + bscale*bias[n] + rscale*resid
template <int MODE>
__global__ void __launch_bounds__(256, 2)
gemm_tn(const float* __restrict__ A, const float* __restrict__ B,
        float* __restrict__ C,
        int M, int N, int K,
        long sA, long sB, long sC,
        float alpha,
        const float* __restrict__ bias, float bscale,
        const float* __restrict__ resid, float rscale,
        float inv_rms)
{
    extern __shared__ float smem[];
    float* As = smem;                   // [2][BM][BKP]
    float* Bs = smem + 2 * STAGE_F;     // [2][BN][BKP]

    const int m0 = blockIdx.y * BM;
    const int n0 = blockIdx.x * BN;
    A += blockIdx.z * sA + (long)m0 * K;
    B += blockIdx.z * sB + (long)n0 * K;
    C += blockIdx.z * sC;
    const float* Rz = (MODE == 1 || MODE == 3) ? resid + blockIdx.z * sC : nullptr;

    const int tid  = threadIdx.x;
    const int lane = tid & 31;
    const int warp = tid >> 5;
    const int wm = warp >> 2;          // 0..1  (64 rows each)
    const int wn = warp & 3;           // 0..3  (32 cols each)
    const int g  = lane >> 2;          // 0..7
    const int t4 = lane & 3;           // 0..3

    const int lrow = tid >> 3;         // 0..31
    const int lcol = (tid & 7) * 4;    // 0..28

    float acc[4][4][4];
#pragma unroll
    for (int i = 0; i < 4; i++)
#pragma unroll
        for (int j = 0; j < 4; j++)
#pragma unroll
            for (int c = 0; c < 4; c++) acc[i][j][c] = 0.f;

    const int KT = K / BK;

    auto issue = [&](int kt, int buf) {
        const float* Ag = A + kt * BK;
        const float* Bg = B + kt * BK;
        float* Asb = As + buf * STAGE_F;
        float* Bsb = Bs + buf * STAGE_F;
#pragma unroll
        for (int i = 0; i < 4; i++) {
            int r = lrow + i * 32;
            unsigned da = (unsigned)__cvta_generic_to_shared(&Asb[r * BKP + lcol]);
            asm volatile("cp.async.cg.shared.global [%0], [%1], 16;\n"
                         :: "r"(da), "l"(Ag + (long)r * K + lcol) : "memory");
            unsigned db = (unsigned)__cvta_generic_to_shared(&Bsb[r * BKP + lcol]);
            asm volatile("cp.async.cg.shared.global [%0], [%1], 16;\n"
                         :: "r"(db), "l"(Bg + (long)r * K + lcol) : "memory");
        }
        asm volatile("cp.async.commit_group;\n" ::: "memory");
    };

    issue(0, 0);

    for (int kt = 0; kt < KT; kt++) {
        int buf = kt & 1;
        asm volatile("cp.async.wait_group 0;\n" ::: "memory");
        __syncthreads();
        if (kt + 1 < KT) issue(kt + 1, buf ^ 1);

        const float* Asb = As + buf * STAGE_F;
        const float* Bsb = Bs + buf * STAGE_F;

#pragma unroll
        for (int ks = 0; ks < 4; ks++) {
            const int kb = ks * 8;
            unsigned af[4][4], bf[4][2];
            // Operands are pre-rounded to tf32: raw fp32 bits ARE valid tf32.
#pragma unroll
            for (int mt = 0; mt < 4; mt++) {
                int r = wm * 64 + mt * 16;
                af[mt][0] = __float_as_uint(Asb[(r + g    ) * BKP + kb + t4]);
                af[mt][1] = __float_as_uint(Asb[(r + g + 8) * BKP + kb + t4]);
                af[mt][2] = __float_as_uint(Asb[(r + g    ) * BKP + kb + t4 + 4]);
                af[mt][3] = __float_as_uint(Asb[(r + g + 8) * BKP + kb + t4 + 4]);
            }
#pragma unroll
            for (int nt = 0; nt < 4; nt++) {
                int c = wn * 32 + nt * 8;
                bf[nt][0] = __float_as_uint(Bsb[(c + g) * BKP + kb + t4]);
                bf[nt][1] = __float_as_uint(Bsb[(c + g) * BKP + kb + t4 + 4]);
            }
#pragma unroll
            for (int mt = 0; mt < 4; mt++)
#pragma unroll
                for (int nt = 0; nt < 4; nt++) {
                    asm volatile(
                        "mma.sync.aligned.m16n8k8.row.col.f32.tf32.tf32.f32 "
                        "{%0,%1,%2,%3}, {%4,%5,%6,%7}, {%8,%9}, {%0,%1,%2,%3};\n"
                        : "+f"(acc[mt][nt][0]), "+f"(acc[mt][nt][1]),
                          "+f"(acc[mt][nt][2]), "+f"(acc[mt][nt][3])
                        : "r"(af[mt][0]), "r"(af[mt][1]), "r"(af[mt][2]), "r"(af[mt][3]),
                          "r"(bf[nt][0]), "r"(bf[nt][1]));
                }
        }
        __syncthreads();
    }

    // ---------------- epilogue ----------------
#pragma unroll
    for (int mt = 0; mt < 4; mt++) {
        int rbase = m0 + wm * 64 + mt * 16;
#pragma unroll
        for (int nt = 0; nt < 4; nt++) {
            int c0 = n0 + wn * 32 + nt * 8 + 2 * t4;
#pragma unroll
            for (int half = 0; half < 2; half++) {
                int r = rbase + g + half * 8;
                float v0 = acc[mt][nt][half * 2 + 0] * alpha;
                float v1 = acc[mt][nt][half * 2 + 1] * alpha;
                if (MODE == 2 || MODE == 3) {
                    v0 += bias[c0] * bscale;
                    v1 += bias[c0 + 1] * bscale;
                }
                if (MODE == 2) {
                    v0 = f2tf32f(v0 * normcdff(v0) * inv_rms);
                    v1 = f2tf32f(v1 * normcdff(v1) * inv_rms);
                }
                long idx = (long)r * N + c0;
                if (MODE == 1 || MODE == 3) {
                    float2 rv = *(const float2*)(Rz + idx);
                    v0 += rv.x * rscale;
                    v1 += rv.y * rscale;
                }
                *(float2*)(C + idx) = make_float2(v0, v1);
            }
        }
    }
}

// ---------------- LayerNorm (rounds output to tf32 for GEMM A operand) -----
__global__ void ln_kernel(const float* __restrict__ xin,
                          const float* __restrict__ w,
                          const float* __restrict__ b,
                          float* __restrict__ y)
{
    __shared__ float red[16];
    const long row = blockIdx.x;
    const float4* xr = (const float4*)(xin + row * HID);
    const int t = threadIdx.x;  // 256 threads, 8 floats each

    float4 v0 = xr[t];
    float4 v1 = xr[t + 256];
    float s  = v0.x + v0.y + v0.z + v0.w + v1.x + v1.y + v1.z + v1.w;
    float sq = v0.x*v0.x + v0.y*v0.y + v0.z*v0.z + v0.w*v0.w
             + v1.x*v1.x + v1.y*v1.y + v1.z*v1.z + v1.w*v1.w;
#pragma unroll
    for (int o = 16; o; o >>= 1) {
        s  += __shfl_xor_sync(0xffffffffu, s,  o);
        sq += __shfl_xor_sync(0xffffffffu, sq, o);
    }
    if ((t & 31) == 0) { red[t >> 5] = s; red[8 + (t >> 5)] = sq; }
    __syncthreads();
    if (t == 0) {
        float S = 0.f, Q = 0.f;
        for (int i = 0; i < 8; i++) { S += red[i]; Q += red[8 + i]; }
        red[0] = S; red[8] = Q;
    }
    __syncthreads();
    const float mean = red[0] * (1.0f / HID);
    float var = red[8] * (1.0f / HID) - mean * mean;
    var = fmaxf(var, 0.0f);
    const float rstd = rsqrtf(var + 1e-5f);

    float4* yr = (float4*)(y + row * HID);
    const float4 w0 = ((const float4*)w)[t];
    const float4 w1 = ((const float4*)w)[t + 256];
    const float4 b0 = ((const float4*)b)[t];
    const float4 b1 = ((const float4*)b)[t + 256];
    float4 o0, o1;
    o0.x = f2tf32f((v0.x - mean) * rstd * w0.x + b0.x);
    o0.y = f2tf32f((v0.y - mean) * rstd * w0.y + b0.y);
    o0.z = f2tf32f((v0.z - mean) * rstd * w0.z + b0.z);
    o0.w = f2tf32f((v0.w - mean) * rstd * w0.w + b0.w);
    o1.x = f2tf32f((v1.x - mean) * rstd * w1.x + b1.x);
    o1.y = f2tf32f((v1.y - mean) * rstd * w1.y + b1.y);
    o1.z = f2tf32f((v1.z - mean) * rstd * w1.z + b1.z);
    o1.w = f2tf32f((v1.w - mean) * rstd * w1.w + b1.w);
    yr[t]       = o0;
    yr[t + 256] = o1;
}

// ---------------- softmax (rounds probs to tf32) ----------------------------
__global__ void softmax_kernel(float* __restrict__ sc)
{
    __shared__ float red[16];
    const size_t row = blockIdx.x;
    float4* p = (float4*)(sc + row * (size_t)SEQL);
    const int t = threadIdx.x;   // 256 threads, 4 floats each

    float4 v = p[t];
    float mx = fmaxf(fmaxf(v.x, v.y), fmaxf(v.z, v.w));
#pragma unroll
    for (int o = 16; o; o >>= 1) mx = fmaxf(mx, __shfl_xor_sync(0xffffffffu, mx, o));
    if ((t & 31) == 0) red[t >> 5] = mx;
    __syncthreads();
    if (t == 0) {
        float m = red[0];
        for (int i = 1; i < 8; i++) m = fmaxf(m, red[i]);
        red[0] = m;
    }
    __syncthreads();
    mx = red[0];

    float e0 = expf(v.x - mx), e1 = expf(v.y - mx);
    float e2 = expf(v.z - mx), e3 = expf(v.w - mx);
    float s = e0 + e1 + e2 + e3;
#pragma unroll
    for (int o = 16; o; o >>= 1) s += __shfl_xor_sync(0xffffffffu, s, o);
    if ((t & 31) == 0) red[8 + (t >> 5)] = s;
    __syncthreads();
    if (t == 0) {
        float S = 0.f;
        for (int i = 0; i < 8; i++) S += red[8 + i];
        red[8] = S;
    }
    __syncthreads();
    const float inv = 1.0f / red[8];

    float4 o;
    o.x = f2tf32f(e0 * inv); o.y = f2tf32f(e1 * inv);
    o.z = f2tf32f(e2 * inv); o.w = f2tf32f(e3 * inv);
    p[t] = o;
}

// ---------------- pack qkv -> Q[bh,s,d], K[bh,s,d], Vt[bh,d,s] (rounded) ----
__global__ void pack_qkv(const float* __restrict__ qkv,
                         float* __restrict__ Qd, float* __restrict__ Kd,
                         float* __restrict__ Vtd)
{
    const int t = blockIdx.x * 256 + threadIdx.x;  // BHTOT*SEQL*DHEAD
    const int d  = t & 127;
    const int s  = (t >> 7) & 1023;
    const int bh = t >> 17;
    const int b  = bh >> 4, h = bh & 15;
    const long m = (long)b * SEQL + s;
    const long base = m * (3 * HID) + (long)h * DHEAD + d;
    const long o = (long)bh * (SEQL * DHEAD) + (long)s * DHEAD + d;
    Qd[o] = f2tf32f(qkv[base]);
    Kd[o] = f2tf32f(qkv[base + HID]);
    Vtd[(long)bh * (SEQL * DHEAD) + (long)d * SEQL + s] = f2tf32f(qkv[base + 2 * HID]);
}

// ---------------- repack ctx[bh,s,d] -> ctxr[b*s, h*d] (rounded) ------------
__global__ void repack_ctx(const float* __restrict__ ctx, float* __restrict__ ctxr)
{
    const int t = blockIdx.x * 256 + threadIdx.x;  // MTOK*HID
    const int hc = t & 2047;
    const int m  = t >> 11;
    const int d = hc & 127, h = hc >> 7;
    const int b = m >> 10, s = m & 1023;
    ctxr[t] = f2tf32f(
        ctx[((long)(b * NHEAD + h)) * (SEQL * DHEAD) + (long)s * DHEAD + d]);
}

// ---------------- weight rounding to tf32 -----------------------------------
__global__ void round_w(const float4* __restrict__ in, float4* __restrict__ out, int n4)
{
    int i = blockIdx.x * 256 + threadIdx.x;
    if (i < n4) {
        float4 v = in[i];
        v.x = f2tf32f(v.x); v.y = f2tf32f(v.y);
        v.z = f2tf32f(v.z); v.w = f2tf32f(v.w);
        out[i] = v;
    }
}

// ---------------- launch ----------------------------------------------------
extern "C" void kernel_launch(void* const* d_in, const int* in_sizes, int n_in,
                              void* d_out, int out_size)
{
    const float* x    = (const float*)d_in[0];
    const float* ln1w = (const float*)d_in[1];
    const float* ln1b = (const float*)d_in[2];
    const float* wqkv = (const float*)d_in[3];
    const float* wo   = (const float*)d_in[4];
    const float* ln2w = (const float*)d_in[5];
    const float* ln2b = (const float*)d_in[6];
    const float* w1   = (const float*)d_in[7];
    const float* b1   = (const float*)d_in[8];
    const float* w2   = (const float*)d_in[9];
    const float* b2   = (const float*)d_in[10];
    float* out = (float*)d_out;

    // GELU_RMS via the same quadrature as the reference
    double ssum = 0.0;
    const double dx = 24.0 / 48000.0;
    for (int i = 0; i <= 48000; i++) {
        double xx  = -12.0 + dx * i;
        double pdf = exp(-0.5 * xx * xx) / sqrt(2.0 * M_PI);
        double cdf = 0.5 * (1.0 + erf(xx / sqrt(2.0)));
        double gg  = xx * cdf;
        ssum += gg * gg * pdf;
    }
    const float inv_rms = (float)(1.0 / sqrt(ssum * dx));

    float* base;
    cudaGetSymbolAddress((void**)&base, g_scratch);
    float* py     = base + OFF_Y;
    float* pqkv   = base + OFF_QKV;
    float* pQ     = base + OFF_Q;
    float* pK     = base + OFF_K;
    float* pVt    = base + OFF_VT;
    float* pS     = base + OFF_S;
    float* pw1r   = base + OFF_W1R;
    float* pw2r   = base + OFF_W2R;
    float* pctx   = base + OFF_CTX;
    float* pctxr  = base + OFF_CTXR;
    float* px2    = base + OFF_X2;
    float* pmlp   = base + OFF_MLP;
    float* pwqkvr = base + OFF_WQKVR;
    float* pwor   = base + OFF_WOR;

    cudaFuncSetAttribute(gemm_tn<0>, cudaFuncAttributeMaxDynamicSharedMemorySize, GEMM_SMEM_BYTES);
    cudaFuncSetAttribute(gemm_tn<1>, cudaFuncAttributeMaxDynamicSharedMemorySize, GEMM_SMEM_BYTES);
    cudaFuncSetAttribute(gemm_tn<2>, cudaFuncAttributeMaxDynamicSharedMemorySize, GEMM_SMEM_BYTES);
    cudaFuncSetAttribute(gemm_tn<3>, cudaFuncAttributeMaxDynamicSharedMemorySize, GEMM_SMEM_BYTES);

    const float rs_h  = (float)(1.0 / sqrt((double)HID));
    const float rs_d  = (float)(1.0 / sqrt((double)DHEAD));
    const float a_ctx = (float)(32.0 / exp(0.5));
    const float a_o   = (float)(sqrt(0.01) / sqrt((double)HID));
    const float r_o   = (float)sqrt(0.99);
    const float a_w2  = (float)(sqrt(0.5) / sqrt((double)(4 * HID)));
    const float b_w2  = (float)sqrt(0.5);
    const float r_w2  = (float)sqrt(0.5);

    // 0. round wqkv/wo to tf32 (into mlp-region aliases; free until step 10)
    round_w<<<(3 * HID * HID / 4 + 255) / 256, 256>>>((const float4*)wqkv, (float4*)pwqkvr, 3 * HID * HID / 4);
    round_w<<<(HID * HID / 4 + 255) / 256, 256>>>((const float4*)wo, (float4*)pwor, HID * HID / 4);

    // 1. LN1 (tf32-rounded output)
    ln_kernel<<<MTOK, 256>>>(x, ln1w, ln1b, py);
    // 2. QKV = LN1(x) @ Wqkv^T * h^-0.5
    gemm_tn<0><<<dim3(48, 32, 1), 256, GEMM_SMEM_BYTES>>>(
        py, pwqkvr, pqkv, MTOK, 3 * HID, HID, 0, 0, 0,
        rs_h, nullptr, 0.f, nullptr, 0.f, 0.f);
    // 3. pack Q/K/Vt (rounded)
    pack_qkv<<<32768, 256>>>(pqkv, pQ, pK, pVt);
    // 4. scores = Q K^T * d^-0.5
    gemm_tn<0><<<dim3(8, 8, BHTOT), 256, GEMM_SMEM_BYTES>>>(
        pQ, pK, pS, SEQL, SEQL, DHEAD,
        (long)SEQL * DHEAD, (long)SEQL * DHEAD, (long)SEQL * SEQL,
        rs_d, nullptr, 0.f, nullptr, 0.f, 0.f);
    // 5. softmax (rounded probs)
    softmax_kernel<<<BHTOT * SEQL, 256>>>(pS);
    // 6. ctx = P @ V * sqrt(S)/sqrt(e)
    gemm_tn<0><<<dim3(1, 8, BHTOT), 256, GEMM_SMEM_BYTES>>>(
        pS, pVt, pctx, SEQL, DHEAD, SEQL,
        (long)SEQL * SEQL, (long)SEQL * DHEAD, (long)SEQL * DHEAD,
        a_ctx, nullptr, 0.f, nullptr, 0.f, 0.f);
    // 6.5 scores no longer needed: round w1/w2 into the S region
    round_w<<<(4 * HID * HID / 4 + 255) / 256, 256>>>((const float4*)w1, (float4*)pw1r, 4 * HID * HID / 4);
    round_w<<<(4 * HID * HID / 4 + 255) / 256, 256>>>((const float4*)w2, (float4*)pw2r, 4 * HID * HID / 4);
    // 7. repack ctx (rounded)
    repack_ctx<<<32768, 256>>>(pctx, pctxr);
    // 8. x2 = (ctx @ Wo^T)*h^-0.5*sqrt(tau) + x*sqrt(1-tau)
    gemm_tn<1><<<dim3(16, 32, 1), 256, GEMM_SMEM_BYTES>>>(
        pctxr, pwor, px2, MTOK, HID, HID, 0, 0, 0,
        a_o, nullptr, 0.f, x, r_o, 0.f);
    // 9. LN2 (rounded output)
    ln_kernel<<<MTOK, 256>>>(px2, ln2w, ln2b, py);
    // 10. mlp = gelu_us( LN2 @ W1^T * h^-0.5 + b1 )  (rounded output)
    gemm_tn<2><<<dim3(64, 32, 1), 256, GEMM_SMEM_BYTES>>>(
        py, pw1r, pmlp, MTOK, 4 * HID, HID, 0, 0, 0,
        rs_h, b1, 1.0f, nullptr, 0.f, inv_rms);
    // 11. out = (mlp @ W2^T * (4h)^-0.5 + b2)*sqrt(.5) + x2*sqrt(.5)
    gemm_tn<3><<<dim3(16, 32, 1), 256, GEMM_SMEM_BYTES>>>(
        pmlp, pw2r, out, MTOK, HID, 4 * HID, 0, 0, 0,
        a_w2, b2, b_w2, px2, r_w2, 0.f);
}